// round 3
// baseline (speedup 1.0000x reference)
#include <cuda_runtime.h>
#include <cuda_bf16.h>
#include <cstdint>
#include <math.h>

#define NROWS 8192
#define DDIM  1024
#define BM    128
#define BK    32
#define SST   40          // padded smem row stride (elements): 80B rows -> conflict-free ldmatrix
#define NTB   (NROWS/BM)  // 64 row-blocks
#define INV_T 14.285714285714285f   // 1/0.07

// ---------------- device scratch (no allocation allowed) ----------------
__device__ __nv_bfloat16 g_zn[(size_t)NROWS * DDIM];  // 16 MB normalized bf16
__device__ float g_norm[NROWS];
__device__ float g_rowsum[NROWS];
__device__ float g_pos[NROWS];

// ---------------- PTX helpers (function-operand style, known-good) ----------------
__device__ __forceinline__ void cp_async_16(uint32_t smem_dst, const void* gmem_src) {
    asm volatile("cp.async.cg.shared.global [%0], [%1], 16;"
                 :: "r"(smem_dst), "l"(gmem_src) : "memory");
}
__device__ __forceinline__ void cp_async_commit() {
    asm volatile("cp.async.commit_group;" ::: "memory");
}
__device__ __forceinline__ void cp_async_wait1() {
    asm volatile("cp.async.wait_group 1;" ::: "memory");
}
__device__ __forceinline__ void cp_async_wait0() {
    asm volatile("cp.async.wait_group 0;" ::: "memory");
}
__device__ __forceinline__ void ldsm_x4(uint32_t& r0, uint32_t& r1, uint32_t& r2, uint32_t& r3,
                                        uint32_t addr) {
    asm volatile("ldmatrix.sync.aligned.m8n8.x4.shared.b16 {%0,%1,%2,%3}, [%4];"
                 : "=r"(r0), "=r"(r1), "=r"(r2), "=r"(r3) : "r"(addr));
}
__device__ __forceinline__ void ldsm_x2(uint32_t& r0, uint32_t& r1, uint32_t addr) {
    asm volatile("ldmatrix.sync.aligned.m8n8.x2.shared.b16 {%0,%1}, [%2];"
                 : "=r"(r0), "=r"(r1) : "r"(addr));
}
__device__ __forceinline__ void mma_bf16(float& c0, float& c1, float& c2, float& c3,
                                         uint32_t a0, uint32_t a1, uint32_t a2, uint32_t a3,
                                         uint32_t b0, uint32_t b1) {
    asm volatile("mma.sync.aligned.m16n8k16.row.col.f32.bf16.bf16.f32 "
                 "{%0,%1,%2,%3}, {%4,%5,%6,%7}, {%8,%9}, {%0,%1,%2,%3};"
                 : "+f"(c0), "+f"(c1), "+f"(c2), "+f"(c3)
                 : "r"(a0), "r"(a1), "r"(a2), "r"(a3), "r"(b0), "r"(b1));
}

// ---------------- kernel 1: normalize rows, zero rowsums ----------------
__global__ __launch_bounds__(256) void norm_kernel(const float* __restrict__ z) {
    int row = blockIdx.x;
    const float* zr = z + (size_t)row * DDIM;
    float ss = 0.f;
    for (int i = threadIdx.x; i < DDIM; i += 256) { float v = zr[i]; ss = fmaf(v, v, ss); }
    #pragma unroll
    for (int o = 16; o; o >>= 1) ss += __shfl_xor_sync(0xffffffffu, ss, o);
    __shared__ float ws[8];
    if ((threadIdx.x & 31) == 0) ws[threadIdx.x >> 5] = ss;
    __syncthreads();
    float tot = ws[0] + ws[1] + ws[2] + ws[3] + ws[4] + ws[5] + ws[6] + ws[7];
    float nrm = fmaxf(sqrtf(tot), 1e-8f);
    float inv = 1.f / nrm;
    __nv_bfloat16* o = g_zn + (size_t)row * DDIM;
    for (int i = threadIdx.x; i < DDIM; i += 256) o[i] = __float2bfloat16(zr[i] * inv);
    if (threadIdx.x == 0) { g_norm[row] = nrm; g_rowsum[row] = 0.f; }
}

// ---------------- kernel 2: pos terms (fp32, one warp per row) ----------------
__global__ __launch_bounds__(256) void pos_kernel(const float* __restrict__ z) {
    int warp = (blockIdx.x * 256 + threadIdx.x) >> 5;
    int lane = threadIdx.x & 31;
    int i = warp;
    int j = (i + NROWS / 2) & (NROWS - 1);   // (i - N/2) mod N == (i + N/2) mod N
    const float* a = z + (size_t)i * DDIM;
    const float* b = z + (size_t)j * DDIM;
    float s = 0.f;
    for (int k = lane; k < DDIM; k += 32) s = fmaf(a[k], b[k], s);
    #pragma unroll
    for (int o = 16; o; o >>= 1) s += __shfl_xor_sync(0xffffffffu, s, o);
    if (lane == 0) g_pos[i] = s / (g_norm[i] * g_norm[j]) * INV_T;
}

// ---------------- kernel 3: triangular gram + fused exp-sum ----------------
__device__ __forceinline__ void load_stage(const __nv_bfloat16* gA, const __nv_bfloat16* gB,
                                           uint32_t sa, uint32_t sb, int kb, int tid) {
    #pragma unroll
    for (int cc = 0; cc < 2; cc++) {
        int id  = tid + 256 * cc;
        int row = id >> 2;
        int kc  = id & 3;
        cp_async_16(sa + (uint32_t)(row * SST + kc * 8) * 2,
                    gA + (size_t)row * DDIM + kb + kc * 8);
        cp_async_16(sb + (uint32_t)(row * SST + kc * 8) * 2,
                    gB + (size_t)row * DDIM + kb + kc * 8);
    }
    cp_async_commit();
}

__global__ __launch_bounds__(256) void gram_kernel() {
    __shared__ __nv_bfloat16 sA[2][BM * SST];
    __shared__ __nv_bfloat16 sB[2][BM * SST];
    __shared__ float s_row[BM];
    __shared__ float s_col[BM];

    // triangular tile decode: blockIdx.x -> (ib, jb), jb >= ib
    int t = blockIdx.x;
    int ib = 0;
    while (t >= NTB - ib) { t -= NTB - ib; ib++; }
    int jb = ib + t;

    const __nv_bfloat16* gA = g_zn + (size_t)ib * BM * DDIM;
    const __nv_bfloat16* gB = g_zn + (size_t)jb * BM * DDIM;

    int tid = threadIdx.x;
    if (tid < BM) { s_row[tid] = 0.f; s_col[tid] = 0.f; }

    uint32_t sAu[2], sBu[2];
    sAu[0] = (uint32_t)__cvta_generic_to_shared(&sA[0][0]);
    sAu[1] = (uint32_t)__cvta_generic_to_shared(&sA[1][0]);
    sBu[0] = (uint32_t)__cvta_generic_to_shared(&sB[0][0]);
    sBu[1] = (uint32_t)__cvta_generic_to_shared(&sB[1][0]);

    int lane = tid & 31, wid = tid >> 5;
    int wm = wid >> 2;   // 0..1 -> 64 rows each
    int wn = wid & 3;    // 0..3 -> 32 cols each

    float acc[4][4][4];
    #pragma unroll
    for (int mt = 0; mt < 4; mt++)
        #pragma unroll
        for (int nt = 0; nt < 4; nt++)
            #pragma unroll
            for (int q = 0; q < 4; q++) acc[mt][nt][q] = 0.f;

    load_stage(gA, gB, sAu[0], sBu[0], 0, tid);

    #pragma unroll 2
    for (int kt = 0; kt < DDIM / BK; kt++) {
        int buf = kt & 1;
        if (kt + 1 < DDIM / BK) {
            load_stage(gA, gB, sAu[buf ^ 1], sBu[buf ^ 1], (kt + 1) * BK, tid);
            cp_async_wait1();
        } else {
            cp_async_wait0();
        }
        __syncthreads();

        #pragma unroll
        for (int ki = 0; ki < 2; ki++) {
            uint32_t af[4][4];
            uint32_t bf[4][2];
            #pragma unroll
            for (int mt = 0; mt < 4; mt++) {
                uint32_t addr_a = sAu[buf] +
                    (uint32_t)(((wm * 64 + mt * 16 + (lane & 15)) * SST + ki * 16 + (lane >> 4) * 8) * 2);
                ldsm_x4(af[mt][0], af[mt][1], af[mt][2], af[mt][3], addr_a);
            }
            #pragma unroll
            for (int nt = 0; nt < 4; nt++) {
                uint32_t addr_b = sBu[buf] +
                    (uint32_t)(((wn * 32 + nt * 8 + (lane & 7)) * SST + ki * 16 + ((lane >> 3) & 1) * 8) * 2);
                ldsm_x2(bf[nt][0], bf[nt][1], addr_b);
            }
            #pragma unroll
            for (int mt = 0; mt < 4; mt++)
                #pragma unroll
                for (int nt = 0; nt < 4; nt++)
                    mma_bf16(acc[mt][nt][0], acc[mt][nt][1], acc[mt][nt][2], acc[mt][nt][3],
                             af[mt][0], af[mt][1], af[mt][2], af[mt][3],
                             bf[nt][0], bf[nt][1]);
        }
        __syncthreads();
    }

    // ---- epilogue: exp + row sums (block ib) and col sums (block jb) ----
    bool diag = (ib == jb);
    float colacc[4][2];
    #pragma unroll
    for (int nt = 0; nt < 4; nt++) { colacc[nt][0] = 0.f; colacc[nt][1] = 0.f; }

    #pragma unroll
    for (int mt = 0; mt < 4; mt++) {
        float r0acc = 0.f, r1acc = 0.f;
        int lr0 = wm * 64 + mt * 16 + (lane >> 2);
        int lr1 = lr0 + 8;
        #pragma unroll
        for (int nt = 0; nt < 4; nt++) {
            int lc0 = wn * 32 + nt * 8 + (lane & 3) * 2;
            int lc1 = lc0 + 1;
            float e00 = __expf(acc[mt][nt][0] * INV_T);
            float e01 = __expf(acc[mt][nt][1] * INV_T);
            float e10 = __expf(acc[mt][nt][2] * INV_T);
            float e11 = __expf(acc[mt][nt][3] * INV_T);
            if (diag) {          // masked diagonal contributes exactly 0
                if (lr0 == lc0) e00 = 0.f;
                if (lr0 == lc1) e01 = 0.f;
                if (lr1 == lc0) e10 = 0.f;
                if (lr1 == lc1) e11 = 0.f;
            }
            r0acc += e00 + e01;
            r1acc += e10 + e11;
            colacc[nt][0] += e00 + e10;
            colacc[nt][1] += e01 + e11;
        }
        r0acc += __shfl_xor_sync(0xffffffffu, r0acc, 1);
        r0acc += __shfl_xor_sync(0xffffffffu, r0acc, 2);
        r1acc += __shfl_xor_sync(0xffffffffu, r1acc, 1);
        r1acc += __shfl_xor_sync(0xffffffffu, r1acc, 2);
        if ((lane & 3) == 0) {
            atomicAdd(&s_row[lr0], r0acc);
            atomicAdd(&s_row[lr1], r1acc);
        }
    }

    if (!diag) {  // symmetric partner rows (block jb) via column sums
        #pragma unroll
        for (int nt = 0; nt < 4; nt++) {
            #pragma unroll
            for (int h = 0; h < 2; h++) {
                float v = colacc[nt][h];
                v += __shfl_xor_sync(0xffffffffu, v, 4);
                v += __shfl_xor_sync(0xffffffffu, v, 8);
                v += __shfl_xor_sync(0xffffffffu, v, 16);
                if (lane < 4) atomicAdd(&s_col[wn * 32 + nt * 8 + lane * 2 + h], v);
            }
        }
    }
    __syncthreads();

    if (tid < BM)
        atomicAdd(&g_rowsum[ib * BM + tid], s_row[tid]);
    else if (!diag)
        atomicAdd(&g_rowsum[jb * BM + (tid - BM)], s_col[tid - BM]);
}

// ---------------- kernel 4: final mean ----------------
__global__ __launch_bounds__(1024) void final_kernel(float* __restrict__ out) {
    float s = 0.f;
    for (int i = threadIdx.x; i < NROWS; i += 1024)
        s += logf(g_rowsum[i]) - g_pos[i];
    #pragma unroll
    for (int o = 16; o; o >>= 1) s += __shfl_xor_sync(0xffffffffu, s, o);
    __shared__ float red[32];
    if ((threadIdx.x & 31) == 0) red[threadIdx.x >> 5] = s;
    __syncthreads();
    if (threadIdx.x < 32) {
        float v = red[threadIdx.x];
        #pragma unroll
        for (int o = 16; o; o >>= 1) v += __shfl_xor_sync(0xffffffffu, v, o);
        if (threadIdx.x == 0) out[0] = v / (float)NROWS;
    }
}

// ---------------- launch ----------------
extern "C" void kernel_launch(void* const* d_in, const int* in_sizes, int n_in,
                              void* d_out, int out_size) {
    (void)in_sizes; (void)n_in; (void)out_size;
    const float* z = (const float*)d_in[0];
    float* out = (float*)d_out;

    norm_kernel<<<NROWS, 256>>>(z);
    pos_kernel<<<NROWS / 8, 256>>>(z);
    gram_kernel<<<NTB * (NTB + 1) / 2, 256>>>();
    final_kernel<<<1, 1024>>>(out);
}

// round 5
// speedup vs baseline: 1.4561x; 1.4561x over previous
#include <cuda_runtime.h>
#include <cuda_bf16.h>
#include <cstdint>
#include <math.h>

#define NROWS 8192
#define DDIM  1024
#define TM    128
#define NTB   (NROWS / TM)          // 64 row-blocks
#define NTILES (NTB * (NTB + 1) / 2) // 2080 triangular tiles
#define NKT   (DDIM / 32)           // 32 k-slices of 32
#define PLANE ((size_t)NROWS * 32)  // bytes per k-slice plane = 262144
#define F8SCALE 16.0f
#define SCALE (14.285714285714285f / (F8SCALE * F8SCALE))  // (1/T)/256

// ---------------- device scratch ----------------
// fragment-packed fp8 copies of normalized z (scaled by 16):
// g_a8: [kt][m_atom(512)][lane(32)][16B]  (A-fragment order for m16n8k32)
// g_b8: [kt][n_atom(1024)][lane(32)][8B]  (B-fragment order)
__device__ uint8_t g_a8[(size_t)NKT * PLANE];
__device__ uint8_t g_b8[(size_t)NKT * PLANE];
__device__ float g_norm[NROWS];
__device__ float g_rowsum[NROWS];
__device__ float g_pos[NROWS];

// ---------------- PTX helpers ----------------
__device__ __forceinline__ uint32_t smem_u32(const void* p) {
    return (uint32_t)__cvta_generic_to_shared(p);
}
__device__ __forceinline__ void cp_async_16(uint32_t dst, const void* src) {
    asm volatile("cp.async.cg.shared.global [%0], [%1], 16;" :: "r"(dst), "l"(src) : "memory");
}
__device__ __forceinline__ void cp_commit() {
    asm volatile("cp.async.commit_group;" ::: "memory");
}
__device__ __forceinline__ void cp_wait2() {
    asm volatile("cp.async.wait_group 2;" ::: "memory");
}
__device__ __forceinline__ void lds128(uint32_t& r0, uint32_t& r1, uint32_t& r2, uint32_t& r3,
                                       uint32_t addr) {
    asm volatile("ld.shared.v4.u32 {%0,%1,%2,%3}, [%4];"
                 : "=r"(r0), "=r"(r1), "=r"(r2), "=r"(r3) : "r"(addr));
}
__device__ __forceinline__ void lds64(uint32_t& r0, uint32_t& r1, uint32_t addr) {
    asm volatile("ld.shared.v2.u32 {%0,%1}, [%2];" : "=r"(r0), "=r"(r1) : "r"(addr));
}
__device__ __forceinline__ void mma_e4m3(float& c0, float& c1, float& c2, float& c3,
                                         uint32_t a0, uint32_t a1, uint32_t a2, uint32_t a3,
                                         uint32_t b0, uint32_t b1) {
    asm volatile("mma.sync.aligned.m16n8k32.row.col.f32.e4m3.e4m3.f32 "
                 "{%0,%1,%2,%3}, {%4,%5,%6,%7}, {%8,%9}, {%0,%1,%2,%3};"
                 : "+f"(c0), "+f"(c1), "+f"(c2), "+f"(c3)
                 : "r"(a0), "r"(a1), "r"(a2), "r"(a3), "r"(b0), "r"(b1));
}
__device__ __forceinline__ uint16_t f2e4m3(float hi, float lo) {
    uint16_t r;
    asm("cvt.rn.satfinite.e4m3x2.f32 %0, %1, %2;" : "=h"(r) : "f"(hi), "f"(lo));
    return r;
}

// ---------------- kernel 1: normalize + fragment-pack fp8 ----------------
__global__ __launch_bounds__(256) void norm_kernel(const float* __restrict__ z) {
    int row = blockIdx.x;
    const float* zr = z + (size_t)row * DDIM;
    float ss = 0.f;
    for (int i = threadIdx.x; i < DDIM; i += 256) { float v = zr[i]; ss = fmaf(v, v, ss); }
    #pragma unroll
    for (int o = 16; o; o >>= 1) ss += __shfl_xor_sync(0xffffffffu, ss, o);
    __shared__ float ws[8];
    if ((threadIdx.x & 31) == 0) ws[threadIdx.x >> 5] = ss;
    __syncthreads();
    float tot = ws[0] + ws[1] + ws[2] + ws[3] + ws[4] + ws[5] + ws[6] + ws[7];
    float nrm = fmaxf(sqrtf(tot), 1e-8f);
    float inv = (1.f / nrm) * F8SCALE;

    // each thread owns one k-quad: k = q*4
    int q = threadIdx.x;
    int k = q * 4;
    float f0 = zr[k] * inv, f1 = zr[k + 1] * inv, f2 = zr[k + 2] * inv, f3 = zr[k + 3] * inv;
    uint32_t word = (uint32_t)f2e4m3(f1, f0) | ((uint32_t)f2e4m3(f3, f2) << 16);

    int kt = q >> 3, tig = q & 3, half = (q >> 2) & 1;
    // A-fragment address
    int atom = row >> 4, rr = row & 15, g = rr & 7, rh = rr >> 3;
    size_t aoff = (size_t)kt * PLANE + (size_t)atom * 512 + (size_t)(g * 4 + tig) * 16
                + (size_t)(half * 2 + rh) * 4;
    *(uint32_t*)(g_a8 + aoff) = word;
    // B-fragment address
    int natom = row >> 3, gb = row & 7;
    size_t boff = (size_t)kt * PLANE + (size_t)natom * 256 + (size_t)(gb * 4 + tig) * 8
                + (size_t)half * 4;
    *(uint32_t*)(g_b8 + boff) = word;

    if (threadIdx.x == 0) { g_norm[row] = nrm; g_rowsum[row] = 0.f; }
}

// ---------------- kernel 2: pos terms (fp32 from raw z) ----------------
__global__ __launch_bounds__(256) void pos_kernel(const float* __restrict__ z) {
    int warp = (blockIdx.x * 256 + threadIdx.x) >> 5;
    int lane = threadIdx.x & 31;
    int i = warp;
    int j = (i + NROWS / 2) & (NROWS - 1);
    const float* a = z + (size_t)i * DDIM;
    const float* b = z + (size_t)j * DDIM;
    float s = 0.f;
    for (int k = lane; k < DDIM; k += 32) s = fmaf(a[k], b[k], s);
    #pragma unroll
    for (int o = 16; o; o >>= 1) s += __shfl_xor_sync(0xffffffffu, s, o);
    if (lane == 0) g_pos[i] = s / (g_norm[i] * g_norm[j]) * 14.285714285714285f;
}

// ---------------- kernel 3: fp8 triangular gram + fused exp-sum ----------------
__global__ __launch_bounds__(256, 2) void gram_kernel() {
    __shared__ uint8_t sA[4][4096];
    __shared__ uint8_t sB[4][4096];
    __shared__ float s_row[TM];
    __shared__ float s_col[TM];

    int tid = threadIdx.x;
    int lane = tid & 31, w = tid >> 5;
    int wm = w >> 2, wn = w & 3;

    // triangular tile decode: jb >= ib
    int t = blockIdx.x, ib = 0;
    while (t >= NTB - ib) { t -= NTB - ib; ib++; }
    int jb = ib + t;
    bool diag = (ib == jb);

    const uint8_t* gA = g_a8 + (size_t)ib * 4096;   // + kt*PLANE
    const uint8_t* gB = g_b8 + (size_t)jb * 4096;

    if (tid < TM) { s_row[tid] = 0.f; s_col[tid] = 0.f; }

    uint32_t sAu = smem_u32(&sA[0][0]);
    uint32_t sBu = smem_u32(&sB[0][0]);

    float acc[4][4][4];
    #pragma unroll
    for (int mt = 0; mt < 4; mt++)
        #pragma unroll
        for (int nt = 0; nt < 4; nt++)
            #pragma unroll
            for (int qq = 0; qq < 4; qq++) acc[mt][nt][qq] = 0.f;

    // prologue: 3 stages in flight
    #pragma unroll
    for (int s = 0; s < 3; s++) {
        cp_async_16(sAu + (uint32_t)(s * 4096 + tid * 16), gA + (size_t)s * PLANE + tid * 16);
        cp_async_16(sBu + (uint32_t)(s * 4096 + tid * 16), gB + (size_t)s * PLANE + tid * 16);
        cp_commit();
    }

    for (int kt = 0; kt < NKT; kt++) {
        cp_wait2();
        __syncthreads();
        int buf = kt & 3;
        uint32_t af[4][4], bf[4][2];
        #pragma unroll
        for (int mt = 0; mt < 4; mt++)
            lds128(af[mt][0], af[mt][1], af[mt][2], af[mt][3],
                   sAu + (uint32_t)(buf * 4096 + (wm * 4 + mt) * 512 + lane * 16));
        #pragma unroll
        for (int nt = 0; nt < 4; nt++)
            lds64(bf[nt][0], bf[nt][1],
                  sBu + (uint32_t)(buf * 4096 + (wn * 4 + nt) * 256 + lane * 8));
        #pragma unroll
        for (int mt = 0; mt < 4; mt++)
            #pragma unroll
            for (int nt = 0; nt < 4; nt++)
                mma_e4m3(acc[mt][nt][0], acc[mt][nt][1], acc[mt][nt][2], acc[mt][nt][3],
                         af[mt][0], af[mt][1], af[mt][2], af[mt][3],
                         bf[nt][0], bf[nt][1]);
        __syncthreads();
        int s = kt + 3;
        if (s < NKT) {
            cp_async_16(sAu + (uint32_t)((s & 3) * 4096 + tid * 16), gA + (size_t)s * PLANE + tid * 16);
            cp_async_16(sBu + (uint32_t)((s & 3) * 4096 + tid * 16), gB + (size_t)s * PLANE + tid * 16);
        }
        cp_commit();   // always commit (empty groups keep the accounting uniform)
    }

    // ---- epilogue: exp + row sums (block ib) and col sums (block jb) ----
    float colacc[4][2];
    #pragma unroll
    for (int nt = 0; nt < 4; nt++) { colacc[nt][0] = 0.f; colacc[nt][1] = 0.f; }

    #pragma unroll
    for (int mt = 0; mt < 4; mt++) {
        float r0acc = 0.f, r1acc = 0.f;
        int lr0 = wm * 64 + mt * 16 + (lane >> 2);
        int lr1 = lr0 + 8;
        #pragma unroll
        for (int nt = 0; nt < 4; nt++) {
            int lc0 = wn * 32 + nt * 8 + (lane & 3) * 2;
            int lc1 = lc0 + 1;
            float e00 = __expf(acc[mt][nt][0] * SCALE);
            float e01 = __expf(acc[mt][nt][1] * SCALE);
            float e10 = __expf(acc[mt][nt][2] * SCALE);
            float e11 = __expf(acc[mt][nt][3] * SCALE);
            if (diag) {
                if (lr0 == lc0) e00 = 0.f;
                if (lr0 == lc1) e01 = 0.f;
                if (lr1 == lc0) e10 = 0.f;
                if (lr1 == lc1) e11 = 0.f;
            }
            r0acc += e00 + e01;
            r1acc += e10 + e11;
            colacc[nt][0] += e00 + e10;
            colacc[nt][1] += e01 + e11;
        }
        r0acc += __shfl_xor_sync(0xffffffffu, r0acc, 1);
        r0acc += __shfl_xor_sync(0xffffffffu, r0acc, 2);
        r1acc += __shfl_xor_sync(0xffffffffu, r1acc, 1);
        r1acc += __shfl_xor_sync(0xffffffffu, r1acc, 2);
        if ((lane & 3) == 0) {
            atomicAdd(&s_row[lr0], r0acc);
            atomicAdd(&s_row[lr1], r1acc);
        }
    }

    if (!diag) {
        #pragma unroll
        for (int nt = 0; nt < 4; nt++) {
            #pragma unroll
            for (int h = 0; h < 2; h++) {
                float v = colacc[nt][h];
                v += __shfl_xor_sync(0xffffffffu, v, 4);
                v += __shfl_xor_sync(0xffffffffu, v, 8);
                v += __shfl_xor_sync(0xffffffffu, v, 16);
                if (lane < 4) atomicAdd(&s_col[wn * 32 + nt * 8 + lane * 2 + h], v);
            }
        }
    }
    __syncthreads();

    if (tid < TM)
        atomicAdd(&g_rowsum[ib * TM + tid], s_row[tid]);
    else if (!diag)
        atomicAdd(&g_rowsum[jb * TM + (tid - TM)], s_col[tid - TM]);
}

// ---------------- kernel 4: final mean ----------------
__global__ __launch_bounds__(1024) void final_kernel(float* __restrict__ out) {
    float s = 0.f;
    for (int i = threadIdx.x; i < NROWS; i += 1024)
        s += __logf(g_rowsum[i]) - g_pos[i];
    #pragma unroll
    for (int o = 16; o; o >>= 1) s += __shfl_xor_sync(0xffffffffu, s, o);
    __shared__ float red[32];
    if ((threadIdx.x & 31) == 0) red[threadIdx.x >> 5] = s;
    __syncthreads();
    if (threadIdx.x < 32) {
        float v = red[threadIdx.x];
        #pragma unroll
        for (int o = 16; o; o >>= 1) v += __shfl_xor_sync(0xffffffffu, v, o);
        if (threadIdx.x == 0) out[0] = v / (float)NROWS;
    }
}

// ---------------- launch ----------------
extern "C" void kernel_launch(void* const* d_in, const int* in_sizes, int n_in,
                              void* d_out, int out_size) {
    (void)in_sizes; (void)n_in; (void)out_size;
    const float* z = (const float*)d_in[0];
    float* out = (float*)d_out;

    norm_kernel<<<NROWS, 256>>>(z);
    pos_kernel<<<NROWS / 8, 256>>>(z);
    gram_kernel<<<NTILES, 256>>>();
    final_kernel<<<1, 1024>>>(out);
}